// round 2
// baseline (speedup 1.0000x reference)
#include <cuda_runtime.h>
#include <cuda_bf16.h>
#include <cstdint>

// ---------------------------------------------------------------------------
// HMM forward (log-likelihood) — GB300 sm_103a
//
// Strategy:
//   Preprocess (cheap kernels):
//     log_pri[j]       = prior - lse(prior)
//     E[j,k] (bf16)    = exp(trans[j,k] - colLSE_k(trans))      (512x512)
//     em_t[m,j] (f32)  = emission[j,m] - rowLSE_j(emission)     (4096x512 transpose)
//   Main recursion: one 4-CTA cluster per batch. CTA r owns rows
//   j in [128r, 128r+128) of E, held ENTIRELY IN REGISTERS (bf16x2).
//   Per step: p[k] = exp(alpha[k]-m) packed bf16x2 in smem; each thread does
//   64 HFMA2; quad-reduce; new alpha exchanged across the cluster via
//   st.shared::cluster into a double-buffered smem array; barrier.cluster.
// ---------------------------------------------------------------------------

#define NSTATE 512
#define MSYM   4096
#define BATCH  64
#define TMAXL  512
#define CSIZE  4
#define ROWS_PER_CTA (NSTATE / CSIZE)   // 128
#define NTHREADS 512

__device__ float        d_row_lse[NSTATE];
__device__ float        d_logpri[NSTATE];
__device__ __nv_bfloat16 d_E[NSTATE * NSTATE];          // 512 KB, [j*512 + k]
__device__ float        d_em_t[(size_t)MSYM * NSTATE];  // 8 MB,  [m*512 + j]

// ---------------------------------------------------------------- helpers
__device__ __forceinline__ __nv_bfloat162 u32_as_bf162(uint32_t u) {
    __nv_bfloat162 r;
    *reinterpret_cast<uint32_t*>(&r) = u;
    return r;
}

__device__ __forceinline__ void st_cluster_f32(uint32_t saddr, uint32_t rank, float v) {
    uint32_t ra;
    asm volatile("mapa.shared::cluster.u32 %0, %1, %2;" : "=r"(ra) : "r"(saddr), "r"(rank));
    asm volatile("st.shared::cluster.u32 [%0], %1;" :: "r"(ra), "r"(__float_as_uint(v)) : "memory");
}

__device__ __forceinline__ void cluster_sync_() {
    asm volatile("barrier.cluster.arrive.aligned;" ::: "memory");  // release
    asm volatile("barrier.cluster.wait.aligned;"   ::: "memory");  // acquire
}

// ---------------------------------------------------------------- prep kernels
__global__ void k_prior(const float* __restrict__ pri) {
    __shared__ float red[16], red2[16];
    int tid = threadIdx.x;
    float v = pri[tid];
    float m = v;
#pragma unroll
    for (int o = 16; o; o >>= 1) m = fmaxf(m, __shfl_xor_sync(0xffffffffu, m, o));
    if ((tid & 31) == 0) red[tid >> 5] = m;
    __syncthreads();
    float mm = red[0];
#pragma unroll
    for (int i = 1; i < 16; i++) mm = fmaxf(mm, red[i]);
    float s = __expf(v - mm);
#pragma unroll
    for (int o = 16; o; o >>= 1) s += __shfl_xor_sync(0xffffffffu, s, o);
    if ((tid & 31) == 0) red2[tid >> 5] = s;
    __syncthreads();
    float tot = 0.f;
#pragma unroll
    for (int i = 0; i < 16; i++) tot += red2[i];
    d_logpri[tid] = v - (mm + __logf(tot));
}

// one block per emission row j; reduce over M=4096
__global__ void k_rowlse(const float* __restrict__ em) {
    __shared__ float red[8], red2[8];
    int j = blockIdx.x;
    int tid = threadIdx.x;  // 256 threads
    const float* row = em + (size_t)j * MSYM;
    float vals[16];
    float m = -1e30f;
#pragma unroll
    for (int i = 0; i < 16; i++) {
        vals[i] = row[tid + 256 * i];
        m = fmaxf(m, vals[i]);
    }
#pragma unroll
    for (int o = 16; o; o >>= 1) m = fmaxf(m, __shfl_xor_sync(0xffffffffu, m, o));
    if ((tid & 31) == 0) red[tid >> 5] = m;
    __syncthreads();
    float mm = red[0];
#pragma unroll
    for (int i = 1; i < 8; i++) mm = fmaxf(mm, red[i]);
    float s = 0.f;
#pragma unroll
    for (int i = 0; i < 16; i++) s += __expf(vals[i] - mm);
#pragma unroll
    for (int o = 16; o; o >>= 1) s += __shfl_xor_sync(0xffffffffu, s, o);
    if ((tid & 31) == 0) red2[tid >> 5] = s;
    __syncthreads();
    if (tid == 0) {
        float tot = 0.f;
#pragma unroll
        for (int i = 0; i < 8; i++) tot += red2[i];
        d_row_lse[j] = mm + __logf(tot);
    }
}

// one block per transition column k; column-softmax -> bf16 E
__global__ void k_colE(const float* __restrict__ tr) {
    __shared__ float red[8], red2[8];
    int k = blockIdx.x;
    int tid = threadIdx.x;  // 256 threads
    float v0 = tr[(size_t)tid * NSTATE + k];
    float v1 = tr[(size_t)(tid + 256) * NSTATE + k];
    float m = fmaxf(v0, v1);
#pragma unroll
    for (int o = 16; o; o >>= 1) m = fmaxf(m, __shfl_xor_sync(0xffffffffu, m, o));
    if ((tid & 31) == 0) red[tid >> 5] = m;
    __syncthreads();
    float mm = red[0];
#pragma unroll
    for (int i = 1; i < 8; i++) mm = fmaxf(mm, red[i]);
    float s = __expf(v0 - mm) + __expf(v1 - mm);
#pragma unroll
    for (int o = 16; o; o >>= 1) s += __shfl_xor_sync(0xffffffffu, s, o);
    if ((tid & 31) == 0) red2[tid >> 5] = s;
    __syncthreads();
    float tot = 0.f;
#pragma unroll
    for (int i = 0; i < 8; i++) tot += red2[i];
    float lse = mm + __logf(tot);
    d_E[(size_t)tid * NSTATE + k]         = __float2bfloat16(__expf(v0 - lse));
    d_E[(size_t)(tid + 256) * NSTATE + k] = __float2bfloat16(__expf(v1 - lse));
}

// transpose emission (N,M) -> em_t (M,N), subtracting row LSE
__global__ void k_emt(const float* __restrict__ em) {
    __shared__ float tile[32][33];
    int m0 = blockIdx.x * 32, j0 = blockIdx.y * 32;
    int tx = threadIdx.x, ty = threadIdx.y;  // (32,8)
#pragma unroll
    for (int yy = 0; yy < 4; yy++) {
        int j = j0 + ty + 8 * yy;
        tile[ty + 8 * yy][tx] = em[(size_t)j * MSYM + m0 + tx];
    }
    __syncthreads();
    float rl = d_row_lse[j0 + tx];
#pragma unroll
    for (int yy = 0; yy < 4; yy++) {
        int m = m0 + ty + 8 * yy;
        d_em_t[(size_t)m * NSTATE + j0 + tx] = tile[tx][ty + 8 * yy] - rl;
    }
}

// ---------------------------------------------------------------- main kernel
__global__ void __launch_bounds__(NTHREADS, 1) __cluster_dims__(CSIZE, 1, 1)
hmm_forward(const int* __restrict__ x, const int* __restrict__ Tarr,
            float* __restrict__ out) {
    __shared__ float sbuf[2][NSTATE];                  // double-buffered alpha
    __shared__ __align__(16) uint32_t p_sm[NSTATE / 2]; // bf16x2-packed p
    __shared__ float wm[16], ws[16];

    const int tid  = threadIdx.x;
    const int lane = tid & 31;
    const int warp = tid >> 5;
    uint32_t rank;
    asm("mov.u32 %0, %%cluster_ctarank;" : "=r"(rank));
    const int b  = blockIdx.x / CSIZE;
    const int Tb = Tarr[b];

    const int j_local = tid >> 2;               // 0..127
    const int q       = tid & 3;                // k-chunk: [q*128, q*128+128)
    const int jg      = (int)rank * ROWS_PER_CTA + j_local;

    // ---- load this thread's 128 E values (64 bf16x2) into registers ----
    __nv_bfloat162 e2[64];
    {
        const uint4* src = reinterpret_cast<const uint4*>(
            d_E + (size_t)jg * NSTATE + q * 128);
#pragma unroll
        for (int i = 0; i < 16; i++) {
            uint4 v = src[i];
            e2[4 * i + 0] = u32_as_bf162(v.x);
            e2[4 * i + 1] = u32_as_bf162(v.y);
            e2[4 * i + 2] = u32_as_bf162(v.z);
            e2[4 * i + 3] = u32_as_bf162(v.w);
        }
    }

    const uint32_t sbuf_addr =
        (uint32_t)__cvta_generic_to_shared(&sbuf[0][0]);

    // ---- t = 0: alpha0 = obs(x0) + log_pri, broadcast to all 4 CTAs ----
    {
        int x0 = x[b * TMAXL];
        if (tid < ROWS_PER_CTA) {
            int j = (int)rank * ROWS_PER_CTA + tid;
            float s0 = d_em_t[(size_t)x0 * NSTATE + j] + d_logpri[j];
            uint32_t addr = sbuf_addr + (uint32_t)j * 4u;  // sbuf[0][j]
#pragma unroll
            for (int r = 0; r < CSIZE; r++) st_cluster_f32(addr, (uint32_t)r, s0);
        }
    }
    cluster_sync_();

    // ---- recursion ----
    int xn = (Tb > 1) ? x[b * TMAXL + 1] : 0;
    for (int t = 1; t < Tb; t++) {
        const float* sb = sbuf[(t - 1) & 1];
        const int xv = xn;
        if (t + 1 < Tb) xn = x[b * TMAXL + t + 1];

        // prefetch observation for this thread's row (quad leader only)
        float obsv = 0.f;
        if (q == 0) obsv = d_em_t[(size_t)xv * NSTATE + jg];

        // phase A: global max m over alpha, then p = exp(alpha - m) in bf16x2
        float mv = sb[tid];
#pragma unroll
        for (int o = 16; o; o >>= 1) mv = fmaxf(mv, __shfl_xor_sync(0xffffffffu, mv, o));
        if (lane == 0) wm[warp] = mv;
        __syncthreads();
        float m = wm[0];
#pragma unroll
        for (int i = 1; i < 16; i++) m = fmaxf(m, wm[i]);
        if (tid < 256) {
            float2 sv = reinterpret_cast<const float2*>(sb)[tid];
            float e0 = __expf(sv.x - m);
            float e1 = __expf(sv.y - m);
            __nv_bfloat162 pp = __floats2bfloat162_rn(e0, e1);
            p_sm[tid] = *reinterpret_cast<uint32_t*>(&pp);
        }
        __syncthreads();

        // phase B: matvec (register E x smem p), 8 short bf16 chains
        __nv_bfloat162 zero2 = __float2bfloat162_rn(0.f);
        __nv_bfloat162 acc[8];
#pragma unroll
        for (int a = 0; a < 8; a++) acc[a] = zero2;
        const uint4* p4 = reinterpret_cast<const uint4*>(p_sm + q * 64);
#pragma unroll
        for (int ii = 0; ii < 16; ii++) {
            uint4 pv = p4[ii];
            acc[(4 * ii + 0) & 7] = __hfma2(e2[4 * ii + 0], u32_as_bf162(pv.x), acc[(4 * ii + 0) & 7]);
            acc[(4 * ii + 1) & 7] = __hfma2(e2[4 * ii + 1], u32_as_bf162(pv.y), acc[(4 * ii + 1) & 7]);
            acc[(4 * ii + 2) & 7] = __hfma2(e2[4 * ii + 2], u32_as_bf162(pv.z), acc[(4 * ii + 2) & 7]);
            acc[(4 * ii + 3) & 7] = __hfma2(e2[4 * ii + 3], u32_as_bf162(pv.w), acc[(4 * ii + 3) & 7]);
        }
        float sum = 0.f;
#pragma unroll
        for (int a = 0; a < 8; a++) {
            float2 f = __bfloat1622float2(acc[a]);
            sum += f.x + f.y;
        }
        sum += __shfl_xor_sync(0xffffffffu, sum, 1);
        sum += __shfl_xor_sync(0xffffffffu, sum, 2);

        if (q == 0) {
            float sn = obsv + m + __logf(sum);
            uint32_t addr = sbuf_addr +
                (uint32_t)(((t & 1) * NSTATE) + jg) * 4u;
#pragma unroll
            for (int r = 0; r < CSIZE; r++) st_cluster_f32(addr, (uint32_t)r, sn);
        }
        cluster_sync_();
    }

    // ---- final logsumexp over alpha[T-1] ----
    {
        const float* sb = sbuf[(Tb - 1) & 1];
        float v = sb[tid];
        float mv = v;
#pragma unroll
        for (int o = 16; o; o >>= 1) mv = fmaxf(mv, __shfl_xor_sync(0xffffffffu, mv, o));
        if (lane == 0) wm[warp] = mv;
        __syncthreads();
        float m = wm[0];
#pragma unroll
        for (int i = 1; i < 16; i++) m = fmaxf(m, wm[i]);
        float e = __expf(v - m);
#pragma unroll
        for (int o = 16; o; o >>= 1) e += __shfl_xor_sync(0xffffffffu, e, o);
        if (lane == 0) ws[warp] = e;
        __syncthreads();
        if (rank == 0 && tid == 0) {
            float tot = 0.f;
#pragma unroll
            for (int i = 0; i < 16; i++) tot += ws[i];
            out[b] = m + __logf(tot);
        }
    }
}

// ---------------------------------------------------------------- launch
extern "C" void kernel_launch(void* const* d_in, const int* in_sizes, int n_in,
                              void* d_out, int out_size) {
    const int*   x   = (const int*)d_in[0];
    const int*   T   = (const int*)d_in[1];
    const float* em  = (const float*)d_in[2];
    const float* tr  = (const float*)d_in[3];
    const float* pri = (const float*)d_in[4];
    float*       out = (float*)d_out;

    k_prior<<<1, NSTATE>>>(pri);
    k_rowlse<<<NSTATE, 256>>>(em);
    k_colE<<<NSTATE, 256>>>(tr);
    k_emt<<<dim3(MSYM / 32, NSTATE / 32), dim3(32, 8)>>>(em);
    hmm_forward<<<BATCH * CSIZE, NTHREADS>>>(x, T, out);
}

// round 3
// speedup vs baseline: 1.2592x; 1.2592x over previous
#include <cuda_runtime.h>
#include <cuda_bf16.h>
#include <cstdint>

// ---------------------------------------------------------------------------
// HMM forward (log-likelihood) — GB300 sm_103a, round 3
//
//   * 4-CTA cluster handles TWO batches (paired by sorted T) -> 32 clusters,
//     single wave (4-CTA capacity = 132 SMs).
//   * E (softmaxed transition, bf16) register-resident: CTA r owns rows
//     [128r,128r+128); thread (j_local=tid>>2, q=tid&3) holds 64 bf16x2.
//   * NO per-step max reduction: alpha normalized by scalar chain
//     c_t = alpha_t[row 0], broadcast via DSMEM ring (4 deep).
//     Producers emit p = exp(alpha - c_prev) directly as bf16 -> consumers
//     do pure HFMA2 matvec, no exp, no block reduce.
//   * One barrier.cluster per step.
// ---------------------------------------------------------------------------

#define NSTATE 512
#define MSYM   4096
#define BATCH  64
#define TMAXL  512
#define CSIZE  4
#define ROWS_PER_CTA (NSTATE / CSIZE)   // 128
#define NTHREADS 512
#define NCLUSTERS (BATCH / 2)           // 32

__device__ float         d_row_lse[NSTATE];
__device__ float         d_logpri[NSTATE];
__device__ __nv_bfloat16 d_E[NSTATE * NSTATE];          // [j*512 + k]
__device__ float         d_em_t[(size_t)MSYM * NSTATE]; // [m*512 + j]
__device__ int           d_perm[BATCH];

// ---------------------------------------------------------------- helpers
__device__ __forceinline__ __nv_bfloat162 u32_as_bf162(uint32_t u) {
    __nv_bfloat162 r;
    *reinterpret_cast<uint32_t*>(&r) = u;
    return r;
}

__device__ __forceinline__ uint32_t mapa_(uint32_t saddr, uint32_t rank) {
    uint32_t ra;
    asm volatile("mapa.shared::cluster.u32 %0, %1, %2;" : "=r"(ra) : "r"(saddr), "r"(rank));
    return ra;
}
__device__ __forceinline__ void st_cl_u16(uint32_t addr, unsigned short v) {
    asm volatile("st.shared::cluster.u16 [%0], %1;" :: "r"(addr), "h"(v) : "memory");
}
__device__ __forceinline__ void st_cl_f32(uint32_t addr, float v) {
    asm volatile("st.shared::cluster.u32 [%0], %1;" :: "r"(addr), "r"(__float_as_uint(v)) : "memory");
}
__device__ __forceinline__ void cluster_sync_() {
    asm volatile("barrier.cluster.arrive.aligned;" ::: "memory");
    asm volatile("barrier.cluster.wait.aligned;"   ::: "memory");
}

// ---------------------------------------------------------------- prep kernels
__global__ void k_prior(const float* __restrict__ pri) {
    __shared__ float red[16], red2[16];
    int tid = threadIdx.x;
    float v = pri[tid];
    float m = v;
#pragma unroll
    for (int o = 16; o; o >>= 1) m = fmaxf(m, __shfl_xor_sync(0xffffffffu, m, o));
    if ((tid & 31) == 0) red[tid >> 5] = m;
    __syncthreads();
    float mm = red[0];
#pragma unroll
    for (int i = 1; i < 16; i++) mm = fmaxf(mm, red[i]);
    float s = __expf(v - mm);
#pragma unroll
    for (int o = 16; o; o >>= 1) s += __shfl_xor_sync(0xffffffffu, s, o);
    if ((tid & 31) == 0) red2[tid >> 5] = s;
    __syncthreads();
    float tot = 0.f;
#pragma unroll
    for (int i = 0; i < 16; i++) tot += red2[i];
    d_logpri[tid] = v - (mm + __logf(tot));
}

__global__ void k_rowlse(const float* __restrict__ em) {
    __shared__ float red[8], red2[8];
    int j = blockIdx.x;
    int tid = threadIdx.x;  // 256
    const float* row = em + (size_t)j * MSYM;
    float vals[16];
    float m = -1e30f;
#pragma unroll
    for (int i = 0; i < 16; i++) {
        vals[i] = row[tid + 256 * i];
        m = fmaxf(m, vals[i]);
    }
#pragma unroll
    for (int o = 16; o; o >>= 1) m = fmaxf(m, __shfl_xor_sync(0xffffffffu, m, o));
    if ((tid & 31) == 0) red[tid >> 5] = m;
    __syncthreads();
    float mm = red[0];
#pragma unroll
    for (int i = 1; i < 8; i++) mm = fmaxf(mm, red[i]);
    float s = 0.f;
#pragma unroll
    for (int i = 0; i < 16; i++) s += __expf(vals[i] - mm);
#pragma unroll
    for (int o = 16; o; o >>= 1) s += __shfl_xor_sync(0xffffffffu, s, o);
    if ((tid & 31) == 0) red2[tid >> 5] = s;
    __syncthreads();
    if (tid == 0) {
        float tot = 0.f;
#pragma unroll
        for (int i = 0; i < 8; i++) tot += red2[i];
        d_row_lse[j] = mm + __logf(tot);
    }
}

__global__ void k_colE(const float* __restrict__ tr) {
    __shared__ float red[8], red2[8];
    int k = blockIdx.x;
    int tid = threadIdx.x;  // 256
    float v0 = tr[(size_t)tid * NSTATE + k];
    float v1 = tr[(size_t)(tid + 256) * NSTATE + k];
    float m = fmaxf(v0, v1);
#pragma unroll
    for (int o = 16; o; o >>= 1) m = fmaxf(m, __shfl_xor_sync(0xffffffffu, m, o));
    if ((tid & 31) == 0) red[tid >> 5] = m;
    __syncthreads();
    float mm = red[0];
#pragma unroll
    for (int i = 1; i < 8; i++) mm = fmaxf(mm, red[i]);
    float s = __expf(v0 - mm) + __expf(v1 - mm);
#pragma unroll
    for (int o = 16; o; o >>= 1) s += __shfl_xor_sync(0xffffffffu, s, o);
    if ((tid & 31) == 0) red2[tid >> 5] = s;
    __syncthreads();
    float tot = 0.f;
#pragma unroll
    for (int i = 0; i < 8; i++) tot += red2[i];
    float lse = mm + __logf(tot);
    d_E[(size_t)tid * NSTATE + k]         = __float2bfloat16(__expf(v0 - lse));
    d_E[(size_t)(tid + 256) * NSTATE + k] = __float2bfloat16(__expf(v1 - lse));
}

__global__ void k_emt(const float* __restrict__ em) {
    __shared__ float tile[32][33];
    int m0 = blockIdx.x * 32, j0 = blockIdx.y * 32;
    int tx = threadIdx.x, ty = threadIdx.y;  // (32,8)
#pragma unroll
    for (int yy = 0; yy < 4; yy++) {
        int j = j0 + ty + 8 * yy;
        tile[ty + 8 * yy][tx] = em[(size_t)j * MSYM + m0 + tx];
    }
    __syncthreads();
    float rl = d_row_lse[j0 + tx];
#pragma unroll
    for (int yy = 0; yy < 4; yy++) {
        int m = m0 + ty + 8 * yy;
        d_em_t[(size_t)m * NSTATE + j0 + tx] = tile[tx][ty + 8 * yy] - rl;
    }
}

// rank-sort of T: pair longest with shortest to balance cluster makespans
__global__ void k_sort(const int* __restrict__ T) {
    int i = threadIdx.x;  // 64
    int ti = T[i];
    int r = 0;
#pragma unroll 8
    for (int j = 0; j < BATCH; j++) {
        int tj = T[j];
        r += (tj < ti) || (tj == ti && j < i);
    }
    d_perm[r] = i;
}

// ---------------------------------------------------------------- main kernel
__global__ void __launch_bounds__(NTHREADS, 1) __cluster_dims__(CSIZE, 1, 1)
hmm_forward(const int* __restrict__ x, const int* __restrict__ Tarr,
            float* __restrict__ out) {
    // p_sm[batch][parity][k] : bf16 p = exp(alpha - c), written via DSMEM
    __shared__ __nv_bfloat16 p_sm[2][2][NSTATE];
    __shared__ float ring[2][4];     // scalar normalizer chain per batch
    __shared__ int   x_sm[2][TMAXL];
    __shared__ float wm[16];

    const int tid  = threadIdx.x;
    const int lane = tid & 31;
    const int warp = tid >> 5;
    uint32_t rank;
    asm("mov.u32 %0, %%cluster_ctarank;" : "=r"(rank));
    const int cl = blockIdx.x / CSIZE;
    const int bA = d_perm[cl];
    const int bB = d_perm[BATCH - 1 - cl];
    const int Ta = Tarr[bA];
    const int Tb = Tarr[bB];
    const int maxT = Ta > Tb ? Ta : Tb;

    const int j_local = tid >> 2;        // 0..127
    const int q       = tid & 3;         // k chunk [q*128, q*128+128)
    const int jg      = (int)rank * ROWS_PER_CTA + j_local;

    // ---- E rows into registers (64 bf16x2) ----
    __nv_bfloat162 e2[64];
    {
        const uint4* src = reinterpret_cast<const uint4*>(
            d_E + (size_t)jg * NSTATE + q * 128);
#pragma unroll
        for (int i = 0; i < 16; i++) {
            uint4 v = src[i];
            e2[4 * i + 0] = u32_as_bf162(v.x);
            e2[4 * i + 1] = u32_as_bf162(v.y);
            e2[4 * i + 2] = u32_as_bf162(v.z);
            e2[4 * i + 3] = u32_as_bf162(v.w);
        }
    }

    // ---- stage observation indices ----
    for (int i = tid; i < Ta; i += NTHREADS) x_sm[0][i] = x[bA * TMAXL + i];
    for (int i = tid; i < Tb; i += NTHREADS) x_sm[1][i] = x[bB * TMAXL + i];

    // ---- init: alpha0 = obs0 + logpri; normalizer a00 = alpha0[0] ----
    const int x0A = x[bA * TMAXL];
    const int x0B = x[bB * TMAXL];
    const float lp0 = d_logpri[0];
    const float a00A = d_em_t[(size_t)x0A * NSTATE] + lp0;
    const float a00B = d_em_t[(size_t)x0B * NSTATE] + lp0;

    const uint32_t pbase = (uint32_t)__cvta_generic_to_shared(&p_sm[0][0][0]);

    if (tid < ROWS_PER_CTA) {
        int j = (int)rank * ROWS_PER_CTA + tid;
        float lpj = d_logpri[j];
        float aA = d_em_t[(size_t)x0A * NSTATE + j] + lpj;
        float aB = d_em_t[(size_t)x0B * NSTATE + j] + lpj;
        __nv_bfloat16 pA = __float2bfloat16(__expf(aA - a00A));
        __nv_bfloat16 pB = __float2bfloat16(__expf(aB - a00B));
        unsigned short bApk = *reinterpret_cast<unsigned short*>(&pA);
        unsigned short bBpk = *reinterpret_cast<unsigned short*>(&pB);
        uint32_t offA = (uint32_t)j * 2u;                    // [0][0][j]
        uint32_t offB = 2u * NSTATE * 2u + (uint32_t)j * 2u; // [1][0][j]
#pragma unroll
        for (int r = 0; r < CSIZE; r++) {
            st_cl_u16(mapa_(pbase + offA, (uint32_t)r), bApk);
            st_cl_u16(mapa_(pbase + offB, (uint32_t)r), bBpk);
        }
    }
    if (tid == 0) { ring[0][0] = a00A; ring[1][0] = a00B; }
    cluster_sync_();

    float cA = a00A, cB = a00B;  // normalizer of currently-live p buffers

    // remote addresses of p_sm[0][0][jg] in each rank (producer side)
    uint32_t remP[CSIZE];
#pragma unroll
    for (int r = 0; r < CSIZE; r++) remP[r] = mapa_(pbase + (uint32_t)jg * 2u, (uint32_t)r);
    const uint32_t ringbase = (uint32_t)__cvta_generic_to_shared(&ring[0][0]);

    // ---- recursion ----
    for (int t = 1; t < maxT; t++) {
        const int par  = t & 1;
        const int prev = par ^ 1;
        const bool actA = t < Ta;
        const bool actB = t < Tb;

        const float c_newA = ring[0][(t - 1) & 3];
        const float c_newB = ring[1][(t - 1) & 3];

        float obsA = 0.f, obsB = 0.f;
        if (q == 0) {
            if (actA) obsA = d_em_t[(size_t)x_sm[0][t] * NSTATE + jg];
            if (actB) obsB = d_em_t[(size_t)x_sm[1][t] * NSTATE + jg];
        }

        // matvec: sum_k E[j,k] * p[k] over this thread's 128-k chunk
        float sumA = 0.f, sumB = 0.f;
        const __nv_bfloat162 zero2 = __float2bfloat162_rn(0.f);
        if (actA) {
            const uint4* p4 = reinterpret_cast<const uint4*>(&p_sm[0][prev][q * 128]);
            __nv_bfloat162 acc[8];
#pragma unroll
            for (int a = 0; a < 8; a++) acc[a] = zero2;
#pragma unroll
            for (int ii = 0; ii < 16; ii++) {
                uint4 pv = p4[ii];
                acc[(4 * ii + 0) & 7] = __hfma2(e2[4 * ii + 0], u32_as_bf162(pv.x), acc[(4 * ii + 0) & 7]);
                acc[(4 * ii + 1) & 7] = __hfma2(e2[4 * ii + 1], u32_as_bf162(pv.y), acc[(4 * ii + 1) & 7]);
                acc[(4 * ii + 2) & 7] = __hfma2(e2[4 * ii + 2], u32_as_bf162(pv.z), acc[(4 * ii + 2) & 7]);
                acc[(4 * ii + 3) & 7] = __hfma2(e2[4 * ii + 3], u32_as_bf162(pv.w), acc[(4 * ii + 3) & 7]);
            }
#pragma unroll
            for (int a = 0; a < 8; a++) {
                float2 f = __bfloat1622float2(acc[a]);
                sumA += f.x + f.y;
            }
        }
        if (actB) {
            const uint4* p4 = reinterpret_cast<const uint4*>(&p_sm[1][prev][q * 128]);
            __nv_bfloat162 acc[8];
#pragma unroll
            for (int a = 0; a < 8; a++) acc[a] = zero2;
#pragma unroll
            for (int ii = 0; ii < 16; ii++) {
                uint4 pv = p4[ii];
                acc[(4 * ii + 0) & 7] = __hfma2(e2[4 * ii + 0], u32_as_bf162(pv.x), acc[(4 * ii + 0) & 7]);
                acc[(4 * ii + 1) & 7] = __hfma2(e2[4 * ii + 1], u32_as_bf162(pv.y), acc[(4 * ii + 1) & 7]);
                acc[(4 * ii + 2) & 7] = __hfma2(e2[4 * ii + 2], u32_as_bf162(pv.z), acc[(4 * ii + 2) & 7]);
                acc[(4 * ii + 3) & 7] = __hfma2(e2[4 * ii + 3], u32_as_bf162(pv.w), acc[(4 * ii + 3) & 7]);
            }
#pragma unroll
            for (int a = 0; a < 8; a++) {
                float2 f = __bfloat1622float2(acc[a]);
                sumB += f.x + f.y;
            }
        }

        // quad reduce (q lanes 4j..4j+3 in same warp)
        sumA += __shfl_xor_sync(0xffffffffu, sumA, 1);
        sumA += __shfl_xor_sync(0xffffffffu, sumA, 2);
        sumB += __shfl_xor_sync(0xffffffffu, sumB, 1);
        sumB += __shfl_xor_sync(0xffffffffu, sumB, 2);

        if (q == 0) {
            if (actA) {
                float sn = obsA + cA + __logf(sumA);
                __nv_bfloat16 pb = __float2bfloat16(__expf(sn - c_newA));
                unsigned short pk = *reinterpret_cast<unsigned short*>(&pb);
                uint32_t off = (uint32_t)par * (NSTATE * 2u);  // [0][par]
#pragma unroll
                for (int r = 0; r < CSIZE; r++) st_cl_u16(remP[r] + off, pk);
                if (rank == 0 && j_local == 0) {
                    uint32_t roff = (uint32_t)(t & 3) * 4u;    // ring[0][t&3]
#pragma unroll
                    for (int r = 0; r < CSIZE; r++) st_cl_f32(mapa_(ringbase + roff, (uint32_t)r), sn);
                }
            }
            if (actB) {
                float sn = obsB + cB + __logf(sumB);
                __nv_bfloat16 pb = __float2bfloat16(__expf(sn - c_newB));
                unsigned short pk = *reinterpret_cast<unsigned short*>(&pb);
                uint32_t off = (2u + (uint32_t)par) * (NSTATE * 2u);  // [1][par]
#pragma unroll
                for (int r = 0; r < CSIZE; r++) st_cl_u16(remP[r] + off, pk);
                if (rank == 0 && j_local == 0) {
                    uint32_t roff = 16u + (uint32_t)(t & 3) * 4u;     // ring[1][t&3]
#pragma unroll
                    for (int r = 0; r < CSIZE; r++) st_cl_f32(mapa_(ringbase + roff, (uint32_t)r), sn);
                }
            }
        }
        if (actA) cA = c_newA;
        if (actB) cB = c_newB;
        cluster_sync_();
    }

    // ---- final: out[b] = c + log( sum_k p[k] ), p from last parity ----
    if (rank == 0) {
#pragma unroll
        for (int beta = 0; beta < 2; beta++) {
            int Tcur = beta ? Tb : Ta;
            int parf = (Tcur - 1) & 1;
            float v = __bfloat162float(p_sm[beta][parf][tid]);
#pragma unroll
            for (int o = 16; o; o >>= 1) v += __shfl_xor_sync(0xffffffffu, v, o);
            if (lane == 0) wm[warp] = v;
            __syncthreads();
            if (tid == 0) {
                float tot = 0.f;
#pragma unroll
                for (int i = 0; i < 16; i++) tot += wm[i];
                out[beta ? bB : bA] = (beta ? cB : cA) + __logf(tot);
            }
            __syncthreads();
        }
    }
}

// ---------------------------------------------------------------- launch
extern "C" void kernel_launch(void* const* d_in, const int* in_sizes, int n_in,
                              void* d_out, int out_size) {
    const int*   x   = (const int*)d_in[0];
    const int*   T   = (const int*)d_in[1];
    const float* em  = (const float*)d_in[2];
    const float* tr  = (const float*)d_in[3];
    const float* pri = (const float*)d_in[4];
    float*       out = (float*)d_out;

    k_prior<<<1, NSTATE>>>(pri);
    k_rowlse<<<NSTATE, 256>>>(em);
    k_colE<<<NSTATE, 256>>>(tr);
    k_emt<<<dim3(MSYM / 32, NSTATE / 32), dim3(32, 8)>>>(em);
    k_sort<<<1, BATCH>>>(T);
    hmm_forward<<<NCLUSTERS * CSIZE, NTHREADS>>>(x, T, out);
}

// round 5
// speedup vs baseline: 2.8352x; 2.2516x over previous
#include <cuda_runtime.h>
#include <cuda_bf16.h>
#include <cstdint>

// ---------------------------------------------------------------------------
// HMM forward (log-likelihood) — GB300 sm_103a, round 5 (re-bench of R4;
// R4 bench died to a container-level infra failure, not a kernel error).
//
//   vs R3 (1343 us):
//   * p_sm chunks padded to 136 bf16 (272 B) -> LDS.128 matvec loads are
//     bank-conflict-free (R3 had 4-way conflicts at 256 B stride).
//   * log2-domain recursion (em_t, logpri pre-scaled by 1/ln2) -> bare
//     ex2/lg2.approx in the serial chain.
//   * bf16 HADD2 tree (8->4) before fp32 unpack in matvec epilogue.
// ---------------------------------------------------------------------------

#define NSTATE 512
#define MSYM   4096
#define BATCH  64
#define TMAXL  512
#define CSIZE  4
#define ROWS_PER_CTA (NSTATE / CSIZE)   // 128
#define NTHREADS 512
#define NCLUSTERS (BATCH / 2)           // 32
#define CHUNK_PAD 136                   // 128 + 8 bf16 -> 272 B (16B-aligned, bank-skewed)

#define INV_LN2 1.4426950408889634f
#define LN2     0.6931471805599453f

__device__ float         d_row_lse[NSTATE];
__device__ float         d_logpri[NSTATE];               // log2 domain
__device__ __nv_bfloat16 d_E[NSTATE * NSTATE];           // [j*512 + k], linear
__device__ float         d_em_t[(size_t)MSYM * NSTATE];  // [m*512 + j], log2 domain
__device__ int           d_perm[BATCH];

// ---------------------------------------------------------------- helpers
__device__ __forceinline__ __nv_bfloat162 u32_as_bf162(uint32_t u) {
    __nv_bfloat162 r;
    *reinterpret_cast<uint32_t*>(&r) = u;
    return r;
}
__device__ __forceinline__ float lg2_(float x) {
    float r; asm("lg2.approx.f32 %0, %1;" : "=f"(r) : "f"(x)); return r;
}
__device__ __forceinline__ float ex2_(float x) {
    float r; asm("ex2.approx.f32 %0, %1;" : "=f"(r) : "f"(x)); return r;
}
__device__ __forceinline__ uint32_t mapa_(uint32_t saddr, uint32_t rank) {
    uint32_t ra;
    asm volatile("mapa.shared::cluster.u32 %0, %1, %2;" : "=r"(ra) : "r"(saddr), "r"(rank));
    return ra;
}
__device__ __forceinline__ void st_cl_u16(uint32_t addr, unsigned short v) {
    asm volatile("st.shared::cluster.u16 [%0], %1;" :: "r"(addr), "h"(v) : "memory");
}
__device__ __forceinline__ void st_cl_f32(uint32_t addr, float v) {
    asm volatile("st.shared::cluster.u32 [%0], %1;" :: "r"(addr), "r"(__float_as_uint(v)) : "memory");
}
__device__ __forceinline__ void cluster_sync_() {
    asm volatile("barrier.cluster.arrive.aligned;" ::: "memory");
    asm volatile("barrier.cluster.wait.aligned;"   ::: "memory");
}

// conflict-free register-E x smem-p partial dot over a 128-k chunk
__device__ __forceinline__ float matvec128(const uint4* __restrict__ p4,
                                           const __nv_bfloat162* __restrict__ e2) {
    const __nv_bfloat162 zero2 = __float2bfloat162_rn(0.f);
    __nv_bfloat162 acc[8];
#pragma unroll
    for (int a = 0; a < 8; a++) acc[a] = zero2;
#pragma unroll
    for (int ii = 0; ii < 16; ii++) {
        uint4 pv = p4[ii];
        acc[(4 * ii + 0) & 7] = __hfma2(e2[4 * ii + 0], u32_as_bf162(pv.x), acc[(4 * ii + 0) & 7]);
        acc[(4 * ii + 1) & 7] = __hfma2(e2[4 * ii + 1], u32_as_bf162(pv.y), acc[(4 * ii + 1) & 7]);
        acc[(4 * ii + 2) & 7] = __hfma2(e2[4 * ii + 2], u32_as_bf162(pv.z), acc[(4 * ii + 2) & 7]);
        acc[(4 * ii + 3) & 7] = __hfma2(e2[4 * ii + 3], u32_as_bf162(pv.w), acc[(4 * ii + 3) & 7]);
    }
    // bf16 tree 8 -> 4, then fp32 finish
    acc[0] = __hadd2(acc[0], acc[4]);
    acc[1] = __hadd2(acc[1], acc[5]);
    acc[2] = __hadd2(acc[2], acc[6]);
    acc[3] = __hadd2(acc[3], acc[7]);
    float2 f0 = __bfloat1622float2(acc[0]);
    float2 f1 = __bfloat1622float2(acc[1]);
    float2 f2 = __bfloat1622float2(acc[2]);
    float2 f3 = __bfloat1622float2(acc[3]);
    return ((f0.x + f0.y) + (f1.x + f1.y)) + ((f2.x + f2.y) + (f3.x + f3.y));
}

// ---------------------------------------------------------------- prep kernels
__global__ void k_prior(const float* __restrict__ pri) {
    __shared__ float red[16], red2[16];
    int tid = threadIdx.x;
    float v = pri[tid];
    float m = v;
#pragma unroll
    for (int o = 16; o; o >>= 1) m = fmaxf(m, __shfl_xor_sync(0xffffffffu, m, o));
    if ((tid & 31) == 0) red[tid >> 5] = m;
    __syncthreads();
    float mm = red[0];
#pragma unroll
    for (int i = 1; i < 16; i++) mm = fmaxf(mm, red[i]);
    float s = __expf(v - mm);
#pragma unroll
    for (int o = 16; o; o >>= 1) s += __shfl_xor_sync(0xffffffffu, s, o);
    if ((tid & 31) == 0) red2[tid >> 5] = s;
    __syncthreads();
    float tot = 0.f;
#pragma unroll
    for (int i = 0; i < 16; i++) tot += red2[i];
    d_logpri[tid] = (v - (mm + __logf(tot))) * INV_LN2;
}

__global__ void k_rowlse(const float* __restrict__ em) {
    __shared__ float red[8], red2[8];
    int j = blockIdx.x;
    int tid = threadIdx.x;  // 256
    const float* row = em + (size_t)j * MSYM;
    float vals[16];
    float m = -1e30f;
#pragma unroll
    for (int i = 0; i < 16; i++) {
        vals[i] = row[tid + 256 * i];
        m = fmaxf(m, vals[i]);
    }
#pragma unroll
    for (int o = 16; o; o >>= 1) m = fmaxf(m, __shfl_xor_sync(0xffffffffu, m, o));
    if ((tid & 31) == 0) red[tid >> 5] = m;
    __syncthreads();
    float mm = red[0];
#pragma unroll
    for (int i = 1; i < 8; i++) mm = fmaxf(mm, red[i]);
    float s = 0.f;
#pragma unroll
    for (int i = 0; i < 16; i++) s += __expf(vals[i] - mm);
#pragma unroll
    for (int o = 16; o; o >>= 1) s += __shfl_xor_sync(0xffffffffu, s, o);
    if ((tid & 31) == 0) red2[tid >> 5] = s;
    __syncthreads();
    if (tid == 0) {
        float tot = 0.f;
#pragma unroll
        for (int i = 0; i < 8; i++) tot += red2[i];
        d_row_lse[j] = mm + __logf(tot);
    }
}

__global__ void k_colE(const float* __restrict__ tr) {
    __shared__ float red[8], red2[8];
    int k = blockIdx.x;
    int tid = threadIdx.x;  // 256
    float v0 = tr[(size_t)tid * NSTATE + k];
    float v1 = tr[(size_t)(tid + 256) * NSTATE + k];
    float m = fmaxf(v0, v1);
#pragma unroll
    for (int o = 16; o; o >>= 1) m = fmaxf(m, __shfl_xor_sync(0xffffffffu, m, o));
    if ((tid & 31) == 0) red[tid >> 5] = m;
    __syncthreads();
    float mm = red[0];
#pragma unroll
    for (int i = 1; i < 8; i++) mm = fmaxf(mm, red[i]);
    float s = __expf(v0 - mm) + __expf(v1 - mm);
#pragma unroll
    for (int o = 16; o; o >>= 1) s += __shfl_xor_sync(0xffffffffu, s, o);
    if ((tid & 31) == 0) red2[tid >> 5] = s;
    __syncthreads();
    float tot = 0.f;
#pragma unroll
    for (int i = 0; i < 8; i++) tot += red2[i];
    float lse = mm + __logf(tot);
    d_E[(size_t)tid * NSTATE + k]         = __float2bfloat16(__expf(v0 - lse));
    d_E[(size_t)(tid + 256) * NSTATE + k] = __float2bfloat16(__expf(v1 - lse));
}

__global__ void k_emt(const float* __restrict__ em) {
    __shared__ float tile[32][33];
    int m0 = blockIdx.x * 32, j0 = blockIdx.y * 32;
    int tx = threadIdx.x, ty = threadIdx.y;  // (32,8)
#pragma unroll
    for (int yy = 0; yy < 4; yy++) {
        int j = j0 + ty + 8 * yy;
        tile[ty + 8 * yy][tx] = em[(size_t)j * MSYM + m0 + tx];
    }
    __syncthreads();
    float rl = d_row_lse[j0 + tx];
#pragma unroll
    for (int yy = 0; yy < 4; yy++) {
        int m = m0 + ty + 8 * yy;
        d_em_t[(size_t)m * NSTATE + j0 + tx] = (tile[tx][ty + 8 * yy] - rl) * INV_LN2;
    }
}

// rank-sort of T: pair longest with shortest to balance cluster makespans
__global__ void k_sort(const int* __restrict__ T) {
    int i = threadIdx.x;  // 64
    int ti = T[i];
    int r = 0;
#pragma unroll 8
    for (int j = 0; j < BATCH; j++) {
        int tj = T[j];
        r += (tj < ti) || (tj == ti && j < i);
    }
    d_perm[r] = i;
}

// ---------------------------------------------------------------- main kernel
__global__ void __launch_bounds__(NTHREADS, 1) __cluster_dims__(CSIZE, 1, 1)
hmm_forward(const int* __restrict__ x, const int* __restrict__ Tarr,
            float* __restrict__ out) {
    // p_sm[batch][parity][chunk q][136 padded] : bf16 p = exp2(alpha2 - c2)
    __shared__ __align__(16) __nv_bfloat16 p_sm[2][2][CSIZE][CHUNK_PAD];
    __shared__ float ring[2][4];     // scalar normalizer chain (log2), per batch
    __shared__ int   x_sm[2][TMAXL];
    __shared__ float wm[16];

    const int tid  = threadIdx.x;
    const int lane = tid & 31;
    const int warp = tid >> 5;
    uint32_t rank;
    asm("mov.u32 %0, %%cluster_ctarank;" : "=r"(rank));
    const int cl = blockIdx.x / CSIZE;
    const int bA = d_perm[cl];
    const int bB = d_perm[BATCH - 1 - cl];
    const int Ta = Tarr[bA];
    const int Tb = Tarr[bB];
    const int maxT = Ta > Tb ? Ta : Tb;

    const int j_local = tid >> 2;        // 0..127
    const int q       = tid & 3;         // k chunk [q*128, q*128+128)
    const int jg      = (int)rank * ROWS_PER_CTA + j_local;

    // ---- E rows into registers (64 bf16x2) ----
    __nv_bfloat162 e2[64];
    {
        const uint4* src = reinterpret_cast<const uint4*>(
            d_E + (size_t)jg * NSTATE + q * 128);
#pragma unroll
        for (int i = 0; i < 16; i++) {
            uint4 v = src[i];
            e2[4 * i + 0] = u32_as_bf162(v.x);
            e2[4 * i + 1] = u32_as_bf162(v.y);
            e2[4 * i + 2] = u32_as_bf162(v.z);
            e2[4 * i + 3] = u32_as_bf162(v.w);
        }
    }

    // ---- stage observation indices ----
    for (int i = tid; i < Ta; i += NTHREADS) x_sm[0][i] = x[bA * TMAXL + i];
    for (int i = tid; i < Tb; i += NTHREADS) x_sm[1][i] = x[bB * TMAXL + i];

    // ---- init: alpha2_0 = obs2(x0) + logpri2; normalizer = alpha2_0[0] ----
    const int x0A = x[bA * TMAXL];
    const int x0B = x[bB * TMAXL];
    const float lp0  = d_logpri[0];
    const float a00A = d_em_t[(size_t)x0A * NSTATE] + lp0;
    const float a00B = d_em_t[(size_t)x0B * NSTATE] + lp0;

    const uint32_t pbase = (uint32_t)__cvta_generic_to_shared(&p_sm[0][0][0][0]);
    // byte strides inside p_sm
    const uint32_t CHUNK_B = CHUNK_PAD * 2u;      // 272
    const uint32_t BUF_B   = CSIZE * CHUNK_B;     // 1088  (one [batch][parity] buffer)

    if (tid < ROWS_PER_CTA) {
        int j = (int)rank * ROWS_PER_CTA + tid;
        float lpj = d_logpri[j];
        float aA = d_em_t[(size_t)x0A * NSTATE + j] + lpj;
        float aB = d_em_t[(size_t)x0B * NSTATE + j] + lpj;
        __nv_bfloat16 pA = __float2bfloat16(ex2_(aA - a00A));
        __nv_bfloat16 pB = __float2bfloat16(ex2_(aB - a00B));
        unsigned short pkA = *reinterpret_cast<unsigned short*>(&pA);
        unsigned short pkB = *reinterpret_cast<unsigned short*>(&pB);
        uint32_t off = rank * CHUNK_B + (uint32_t)tid * 2u;   // chunk=rank, idx=tid
#pragma unroll
        for (int r = 0; r < CSIZE; r++) {
            uint32_t ra = mapa_(pbase + off, (uint32_t)r);
            st_cl_u16(ra, pkA);                 // [0][0]
            st_cl_u16(ra + 2u * BUF_B, pkB);    // [1][0]
        }
    }
    if (tid == 0) { ring[0][0] = a00A; ring[1][0] = a00B; }
    cluster_sync_();

    float cA = a00A, cB = a00B;  // normalizer (log2) of currently-live p buffers

    // remote addresses of this producer's slot (chunk=my rank, idx=j_local)
    uint32_t remP[CSIZE];
#pragma unroll
    for (int r = 0; r < CSIZE; r++)
        remP[r] = mapa_(pbase + rank * CHUNK_B + (uint32_t)j_local * 2u, (uint32_t)r);
    const uint32_t ringbase = (uint32_t)__cvta_generic_to_shared(&ring[0][0]);

    // ---- recursion ----
    for (int t = 1; t < maxT; t++) {
        const int par  = t & 1;
        const int prev = par ^ 1;
        const bool actA = t < Ta;
        const bool actB = t < Tb;

        const float c_newA = ring[0][(t - 1) & 3];
        const float c_newB = ring[1][(t - 1) & 3];

        float obsA = 0.f, obsB = 0.f;
        if (q == 0) {
            if (actA) obsA = d_em_t[(size_t)x_sm[0][t] * NSTATE + jg];
            if (actB) obsB = d_em_t[(size_t)x_sm[1][t] * NSTATE + jg];
        }

        float sumA = 0.f, sumB = 0.f;
        if (actA)
            sumA = matvec128(reinterpret_cast<const uint4*>(&p_sm[0][prev][q][0]), e2);
        if (actB)
            sumB = matvec128(reinterpret_cast<const uint4*>(&p_sm[1][prev][q][0]), e2);

        // quad reduce (q lanes are adjacent in-warp)
        sumA += __shfl_xor_sync(0xffffffffu, sumA, 1);
        sumA += __shfl_xor_sync(0xffffffffu, sumA, 2);
        sumB += __shfl_xor_sync(0xffffffffu, sumB, 1);
        sumB += __shfl_xor_sync(0xffffffffu, sumB, 2);

        if (q == 0) {
            if (actA) {
                float sn = obsA + cA + lg2_(sumA);
                __nv_bfloat16 pb = __float2bfloat16(ex2_(sn - c_newA));
                unsigned short pk = *reinterpret_cast<unsigned short*>(&pb);
                uint32_t off = (uint32_t)par * BUF_B;                 // [0][par]
#pragma unroll
                for (int r = 0; r < CSIZE; r++) st_cl_u16(remP[r] + off, pk);
                if (rank == 0 && j_local == 0) {
                    uint32_t roff = (uint32_t)(t & 3) * 4u;           // ring[0][t&3]
#pragma unroll
                    for (int r = 0; r < CSIZE; r++) st_cl_f32(mapa_(ringbase + roff, (uint32_t)r), sn);
                }
            }
            if (actB) {
                float sn = obsB + cB + lg2_(sumB);
                __nv_bfloat16 pb = __float2bfloat16(ex2_(sn - c_newB));
                unsigned short pk = *reinterpret_cast<unsigned short*>(&pb);
                uint32_t off = (2u + (uint32_t)par) * BUF_B;          // [1][par]
#pragma unroll
                for (int r = 0; r < CSIZE; r++) st_cl_u16(remP[r] + off, pk);
                if (rank == 0 && j_local == 0) {
                    uint32_t roff = 16u + (uint32_t)(t & 3) * 4u;     // ring[1][t&3]
#pragma unroll
                    for (int r = 0; r < CSIZE; r++) st_cl_f32(mapa_(ringbase + roff, (uint32_t)r), sn);
                }
            }
        }
        if (actA) cA = c_newA;
        if (actB) cB = c_newB;
        cluster_sync_();
    }

    // ---- final: out[b] = ln2 * ( c2 + log2( sum_k p[k] ) ) ----
    if (rank == 0) {
#pragma unroll
        for (int beta = 0; beta < 2; beta++) {
            int Tcur = beta ? Tb : Ta;
            int parf = (Tcur - 1) & 1;
            float v = __bfloat162float(p_sm[beta][parf][tid >> 7][tid & 127]);
#pragma unroll
            for (int o = 16; o; o >>= 1) v += __shfl_xor_sync(0xffffffffu, v, o);
            if (lane == 0) wm[warp] = v;
            __syncthreads();
            if (tid == 0) {
                float tot = 0.f;
#pragma unroll
                for (int i = 0; i < 16; i++) tot += wm[i];
                out[beta ? bB : bA] = ((beta ? cB : cA) + lg2_(tot)) * LN2;
            }
            __syncthreads();
        }
    }
}

// ---------------------------------------------------------------- launch
extern "C" void kernel_launch(void* const* d_in, const int* in_sizes, int n_in,
                              void* d_out, int out_size) {
    const int*   x   = (const int*)d_in[0];
    const int*   T   = (const int*)d_in[1];
    const float* em  = (const float*)d_in[2];
    const float* tr  = (const float*)d_in[3];
    const float* pri = (const float*)d_in[4];
    float*       out = (float*)d_out;

    k_prior<<<1, NSTATE>>>(pri);
    k_rowlse<<<NSTATE, 256>>>(em);
    k_colE<<<NSTATE, 256>>>(tr);
    k_emt<<<dim3(MSYM / 32, NSTATE / 32), dim3(32, 8)>>>(em);
    k_sort<<<1, BATCH>>>(T);
    hmm_forward<<<NCLUSTERS * CSIZE, NTHREADS>>>(x, T, out);
}